// round 2
// baseline (speedup 1.0000x reference)
#include <cuda_runtime.h>

// RegionIntegrator: fixed geometry
//   B=4, N_REG=225 (15x15 grid, step 32), C=16, RS=64, H=W=512, pad=0.
// Gather formulation: each output pixel (i,j) is covered by at most 2x2
// regions whose starts are multiples of 32 in [p-63, p] clamped to [0,448].
// Coverage set is constant within each aligned 32-px span per axis, so an
// even/odd row pair (i, i+1) always shares the same region set and count.
// Each thread computes TWO output rows at one j4 quad: 2x index-math
// amortization and up to 8 independent LDG.128 in flight.

#define RI_B   4
#define RI_N   225
#define RI_C   16
#define RI_RS  64
#define RI_HW  512
#define RI_W4  128  // 512 / 4
#define RI_H2  256  // 512 / 2 row-pairs

__global__ __launch_bounds__(256) void region_gather2_kernel(
    const float* __restrict__ regions, float* __restrict__ out)
{
    int idx = blockIdx.x * blockDim.x + threadIdx.x;   // over B*C*(H/2)*(W/4) = 2,097,152
    int j4 = (idx & (RI_W4 - 1)) << 2;                 // 0..508, multiple of 4
    int i  = ((idx >> 7) & (RI_H2 - 1)) << 1;          // even row 0..510
    int bc = idx >> 15;                                 // b*16 + c
    int c  = bc & (RI_C - 1);
    int b  = bc >> 4;

    // Covering row starts: multiples of 32 in [max(0,i-63), min(448,i)].
    // Same set for rows i and i+1 (pair never straddles a 32-boundary).
    int lo_i       = i - 63; if (lo_i < 0) lo_i = 0;
    int hi_i       = i < 448 ? i : 448;
    int s_first_i  = ((lo_i + 31) >> 5) << 5;
    int s_last_i   = (hi_i >> 5) << 5;

    int lo_j       = j4 - 63; if (lo_j < 0) lo_j = 0;
    int hi_j       = j4 < 448 ? j4 : 448;
    int s_first_j  = ((lo_j + 31) >> 5) << 5;
    int s_last_j   = (hi_j >> 5) << 5;

    bool two_i = (s_last_i != s_first_i);
    bool two_j = (s_last_j != s_first_j);

    // regions[((b*225 + n)*16 + c) * 4096 + ri*64 + rj]
    long base_bc = ((long)b * RI_N) * RI_C + c;

    float4 a0 = make_float4(0.f, 0.f, 0.f, 0.f);   // row i
    float4 a1 = make_float4(0.f, 0.f, 0.f, 0.f);   // row i+1

    // Region (s_first_i, s_first_j): always valid. Row i+1 is +64 floats.
    {
        int n  = (s_first_i >> 5) * 15 + (s_first_j >> 5);
        long off = (base_bc + (long)n * RI_C) * 4096 + ((i - s_first_i) << 6) + (j4 - s_first_j);
        float4 v0 = *reinterpret_cast<const float4*>(regions + off);
        float4 v1 = *reinterpret_cast<const float4*>(regions + off + 64);
        a0.x += v0.x; a0.y += v0.y; a0.z += v0.z; a0.w += v0.w;
        a1.x += v1.x; a1.y += v1.y; a1.z += v1.z; a1.w += v1.w;
    }
    if (two_j) {
        int n  = (s_first_i >> 5) * 15 + (s_last_j >> 5);
        long off = (base_bc + (long)n * RI_C) * 4096 + ((i - s_first_i) << 6) + (j4 - s_last_j);
        float4 v0 = *reinterpret_cast<const float4*>(regions + off);
        float4 v1 = *reinterpret_cast<const float4*>(regions + off + 64);
        a0.x += v0.x; a0.y += v0.y; a0.z += v0.z; a0.w += v0.w;
        a1.x += v1.x; a1.y += v1.y; a1.z += v1.z; a1.w += v1.w;
    }
    if (two_i) {
        int n  = (s_last_i >> 5) * 15 + (s_first_j >> 5);
        long off = (base_bc + (long)n * RI_C) * 4096 + ((i - s_last_i) << 6) + (j4 - s_first_j);
        float4 v0 = *reinterpret_cast<const float4*>(regions + off);
        float4 v1 = *reinterpret_cast<const float4*>(regions + off + 64);
        a0.x += v0.x; a0.y += v0.y; a0.z += v0.z; a0.w += v0.w;
        a1.x += v1.x; a1.y += v1.y; a1.z += v1.z; a1.w += v1.w;
    }
    if (two_i && two_j) {
        int n  = (s_last_i >> 5) * 15 + (s_last_j >> 5);
        long off = (base_bc + (long)n * RI_C) * 4096 + ((i - s_last_i) << 6) + (j4 - s_last_j);
        float4 v0 = *reinterpret_cast<const float4*>(regions + off);
        float4 v1 = *reinterpret_cast<const float4*>(regions + off + 64);
        a0.x += v0.x; a0.y += v0.y; a0.z += v0.z; a0.w += v0.w;
        a1.x += v1.x; a1.y += v1.y; a1.z += v1.z; a1.w += v1.w;
    }

    int cnt = (two_i ? 2 : 1) * (two_j ? 2 : 1);   // 1, 2 or 4
    float inv = (cnt == 1) ? 1.0f : (cnt == 2 ? 0.5f : 0.25f);
    a0.x *= inv; a0.y *= inv; a0.z *= inv; a0.w *= inv;
    a1.x *= inv; a1.y *= inv; a1.z *= inv; a1.w *= inv;

    long oidx = ((long)bc * RI_HW + i) * RI_HW + j4;
    *reinterpret_cast<float4*>(out + oidx) = a0;
    *reinterpret_cast<float4*>(out + oidx + RI_HW) = a1;
}

extern "C" void kernel_launch(void* const* d_in, const int* in_sizes, int n_in,
                              void* d_out, int out_size)
{
    const float* regions = (const float*)d_in[0];
    float* out = (float*)d_out;
    // total threads: B*C*(H/2)*(W/4) = 4 * 16 * 256 * 128 = 2,097,152
    int total = RI_B * RI_C * RI_H2 * RI_W4;
    int block = 256;
    int grid = total / block;   // 8192
    region_gather2_kernel<<<grid, block>>>(regions, out);
}